// round 1
// baseline (speedup 1.0000x reference)
#include <cuda_runtime.h>
#include <cstdint>

#define NP 100000
#define NA 50000
#define DIM 128
#define EE  500000

// Scratch (allocation-guard-safe __device__ globals)
__device__ float g_Hc[(size_t)NP * DIM];   // x_paper  @ W_cites
__device__ float g_Hw[(size_t)NA * DIM];   // x_author @ W_writes
__device__ float g_deg[NP];                // deg_c + deg_w

// ---------------------------------------------------------------------------
__global__ void __launch_bounds__(256) zero_deg_kernel() {
    int i = blockIdx.x * 256 + threadIdx.x;
    if (i < NP) g_deg[i] = 0.0f;
}

// ---------------------------------------------------------------------------
// Y[n_rows,128] = X[n_rows,128] @ W[128,128]
// Block: 256 threads, 64 rows per block. W + X-tile staged in dynamic smem.
// Thread (tx = lane 0..31 -> 4 cols, ty = warp 0..7 -> 8 rows strided by 8).
__global__ void __launch_bounds__(256) gemm128_kernel(
    const float* __restrict__ X, const float* __restrict__ W,
    float* __restrict__ Y, int n_rows)
{
    extern __shared__ float smem[];
    float* Ws = smem;              // 128 x 128
    float* Xs = smem + DIM * DIM;  // 64 x 128

    const int tid  = threadIdx.x;
    const int tx   = tid & 31;
    const int ty   = tid >> 5;
    const int row0 = blockIdx.x * 64;

    // Stage W: 4096 float4
    for (int i = tid; i < DIM * 32; i += 256)
        ((float4*)Ws)[i] = ((const float4*)W)[i];

    // Stage X tile: 64 rows x 32 float4
    for (int i = tid; i < 64 * 32; i += 256) {
        int r  = i >> 5;
        int gr = row0 + r;
        float4 v = make_float4(0.f, 0.f, 0.f, 0.f);
        if (gr < n_rows) v = ((const float4*)(X + (size_t)gr * DIM))[i & 31];
        ((float4*)Xs)[i] = v;
    }
    __syncthreads();

    float acc[8][4];
    #pragma unroll
    for (int i = 0; i < 8; i++) {
        acc[i][0] = 0.f; acc[i][1] = 0.f; acc[i][2] = 0.f; acc[i][3] = 0.f;
    }

    #pragma unroll 4
    for (int k = 0; k < DIM; k++) {
        float4 wv = ((const float4*)(Ws + k * DIM))[tx];   // conflict-free
        #pragma unroll
        for (int i = 0; i < 8; i++) {
            float xv = Xs[(ty + 8 * i) * DIM + k];          // warp broadcast
            acc[i][0] += xv * wv.x;
            acc[i][1] += xv * wv.y;
            acc[i][2] += xv * wv.z;
            acc[i][3] += xv * wv.w;
        }
    }

    #pragma unroll
    for (int i = 0; i < 8; i++) {
        int gr = row0 + ty + 8 * i;
        if (gr < n_rows)
            ((float4*)(Y + (size_t)gr * DIM))[tx] =
                make_float4(acc[i][0], acc[i][1], acc[i][2], acc[i][3]);
    }
}

// ---------------------------------------------------------------------------
// One warp per edge: gather 512B row H[src], atomic-add into out[dst].
// Lane 0 also counts the edge into g_deg[dst].
__global__ void __launch_bounds__(256) scatter_kernel(
    const float* __restrict__ H, const int* __restrict__ src,
    const int* __restrict__ dst, float* __restrict__ out, int nE)
{
    int e    = (blockIdx.x * 256 + threadIdx.x) >> 5;
    int lane = threadIdx.x & 31;
    if (e >= nE) return;

    int s = __ldg(src + e);
    int d = __ldg(dst + e);

    float4 v = ((const float4*)(H + (size_t)s * DIM))[lane];
    float* op = out + (size_t)d * DIM + lane * 4;
    atomicAdd(op + 0, v.x);
    atomicAdd(op + 1, v.y);
    atomicAdd(op + 2, v.z);
    atomicAdd(op + 3, v.w);

    if (lane == 0) atomicAdd(&g_deg[d], 1.0f);
}

// ---------------------------------------------------------------------------
// out = relu(out / (deg + 1) + bias), in place. One thread per float4.
__global__ void __launch_bounds__(256) finalize_kernel(
    float* __restrict__ out, const float* __restrict__ bias)
{
    int i = blockIdx.x * 256 + threadIdx.x;
    if (i >= NP * 32) return;
    int row = i >> 5;
    int c4  = i & 31;

    float inv = 1.0f / (g_deg[row] + 1.0f);
    float4 v = ((float4*)out)[i];
    float4 b = ((const float4*)bias)[c4];
    v.x = fmaxf(fmaf(v.x, inv, b.x), 0.f);
    v.y = fmaxf(fmaf(v.y, inv, b.y), 0.f);
    v.z = fmaxf(fmaf(v.z, inv, b.z), 0.f);
    v.w = fmaxf(fmaf(v.w, inv, b.w), 0.f);
    ((float4*)out)[i] = v;
}

// ---------------------------------------------------------------------------
extern "C" void kernel_launch(void* const* d_in, const int* in_sizes, int n_in,
                              void* d_out, int out_size)
{
    const float* x_paper    = (const float*)d_in[0];
    const float* x_author   = (const float*)d_in[1];
    const float* W_cites    = (const float*)d_in[2];
    const float* W_writes   = (const float*)d_in[3];
    const float* W_self     = (const float*)d_in[4];
    const float* bias       = (const float*)d_in[5];
    const int*   cites_src  = (const int*)d_in[6];
    const int*   cites_dst  = (const int*)d_in[7];
    const int*   writes_src = (const int*)d_in[8];
    const int*   writes_dst = (const int*)d_in[9];
    float*       out        = (float*)d_out;

    const int smem_bytes = (DIM * DIM + 64 * DIM) * (int)sizeof(float); // 98304
    cudaFuncSetAttribute(gemm128_kernel,
                         cudaFuncAttributeMaxDynamicSharedMemorySize, smem_bytes);

    void *pHc = nullptr, *pHw = nullptr;
    cudaGetSymbolAddress(&pHc, g_Hc);
    cudaGetSymbolAddress(&pHw, g_Hw);

    // 1. degree accumulator -> 0
    zero_deg_kernel<<<(NP + 255) / 256, 256>>>();

    // 2. GEMMs: self-transform writes d_out directly (acts as accumulator init)
    gemm128_kernel<<<(NP + 63) / 64, 256, smem_bytes>>>(x_paper,  W_self,   out,          NP);
    gemm128_kernel<<<(NP + 63) / 64, 256, smem_bytes>>>(x_paper,  W_cites,  (float*)pHc, NP);
    gemm128_kernel<<<(NA + 63) / 64, 256, smem_bytes>>>(x_author, W_writes, (float*)pHw, NA);

    // 3. edge scatter (atomics into d_out) + fused degree counting
    scatter_kernel<<<EE / 8, 256>>>((const float*)pHc, cites_src,  cites_dst,  out, EE);
    scatter_kernel<<<EE / 8, 256>>>((const float*)pHw, writes_src, writes_dst, out, EE);

    // 4. mean + bias + relu
    finalize_kernel<<<(NP * 32 + 255) / 256, 256>>>(out, bias);
}

// round 2
// speedup vs baseline: 1.3889x; 1.3889x over previous
#include <cuda_runtime.h>
#include <cstdint>

#define NP 100000
#define NA 50000
#define DIM 128
#define EE  500000

// Scratch (allocation-guard-safe __device__ globals)
__device__ float g_Hc[(size_t)NP * DIM];   // x_paper  @ W_cites
__device__ float g_Hw[(size_t)NA * DIM];   // x_author @ W_writes
__device__ float g_deg[NP];                // deg_c + deg_w

// ---------------------------------------------------------------------------
__global__ void __launch_bounds__(256) zero_deg_kernel() {
    int i = blockIdx.x * 256 + threadIdx.x;
    if (i < NP) g_deg[i] = 0.0f;
}

// ---------------------------------------------------------------------------
// Y[n_rows,128] = X[n_rows,128] @ W[128,128]
// 256 threads, 64 rows/block. W(64KB)+X-tile(32KB) in dynamic smem -> 2 CTA/SM.
// Thread (tx,ty): tx -> 4 output cols, ty -> 8 rows (stride 8).
// Inner loop: k in groups of 4 -> 12x LDS.128 per 128 FFMA.
__global__ void __launch_bounds__(256, 2) gemm128_kernel(
    const float* __restrict__ X, const float* __restrict__ W,
    float* __restrict__ Y, int n_rows)
{
    extern __shared__ float smem[];
    float4* Ws4 = (float4*)smem;                    // 128 rows x 32 float4
    float4* Xs4 = (float4*)(smem + DIM * DIM);      // 64  rows x 32 float4

    const int tid  = threadIdx.x;
    const int tx   = tid & 31;
    const int ty   = tid >> 5;
    const int row0 = blockIdx.x * 64;

    for (int i = tid; i < DIM * 32; i += 256)
        Ws4[i] = ((const float4*)W)[i];

    for (int i = tid; i < 64 * 32; i += 256) {
        int gr = row0 + (i >> 5);
        float4 v = make_float4(0.f, 0.f, 0.f, 0.f);
        if (gr < n_rows) v = ((const float4*)(X + (size_t)gr * DIM))[i & 31];
        Xs4[i] = v;
    }
    __syncthreads();

    float acc[8][4];
    #pragma unroll
    for (int i = 0; i < 8; i++)
        acc[i][0] = acc[i][1] = acc[i][2] = acc[i][3] = 0.f;

    #pragma unroll 2
    for (int k4 = 0; k4 < 32; k4++) {
        float4 w0 = Ws4[(k4 * 4 + 0) * 32 + tx];
        float4 w1 = Ws4[(k4 * 4 + 1) * 32 + tx];
        float4 w2 = Ws4[(k4 * 4 + 2) * 32 + tx];
        float4 w3 = Ws4[(k4 * 4 + 3) * 32 + tx];
        #pragma unroll
        for (int i = 0; i < 8; i++) {
            float4 xv = Xs4[(ty + 8 * i) * 32 + k4];   // warp broadcast
            acc[i][0] += xv.x * w0.x + xv.y * w1.x + xv.z * w2.x + xv.w * w3.x;
            acc[i][1] += xv.x * w0.y + xv.y * w1.y + xv.z * w2.y + xv.w * w3.y;
            acc[i][2] += xv.x * w0.z + xv.y * w1.z + xv.z * w2.z + xv.w * w3.z;
            acc[i][3] += xv.x * w0.w + xv.y * w1.w + xv.z * w2.w + xv.w * w3.w;
        }
    }

    #pragma unroll
    for (int i = 0; i < 8; i++) {
        int gr = row0 + ty + 8 * i;
        if (gr < n_rows)
            ((float4*)(Y + (size_t)gr * DIM))[tx] =
                make_float4(acc[i][0], acc[i][1], acc[i][2], acc[i][3]);
    }
}

// ---------------------------------------------------------------------------
// One warp per edge: gather 512B row H[src]; one red.v4 per lane into out[dst].
__global__ void __launch_bounds__(256) scatter_kernel(
    const float* __restrict__ H, const int* __restrict__ src,
    const int* __restrict__ dst, float* __restrict__ out, int nE)
{
    int e    = (blockIdx.x * 256 + threadIdx.x) >> 5;
    int lane = threadIdx.x & 31;
    if (e >= nE) return;

    int s = __ldg(src + e);
    int d = __ldg(dst + e);

    float4 v = ((const float4*)(H + (size_t)s * DIM))[lane];
    float* op = out + (size_t)d * DIM + lane * 4;
    asm volatile("red.global.add.v4.f32 [%0], {%1, %2, %3, %4};"
                 :: "l"(op), "f"(v.x), "f"(v.y), "f"(v.z), "f"(v.w)
                 : "memory");

    if (lane == 0)
        asm volatile("red.global.add.f32 [%0], %1;"
                     :: "l"(&g_deg[d]), "f"(1.0f) : "memory");
}

// ---------------------------------------------------------------------------
// out = relu(out / (deg + 1) + bias), in place. One thread per float4.
__global__ void __launch_bounds__(256) finalize_kernel(
    float* __restrict__ out, const float* __restrict__ bias)
{
    int i = blockIdx.x * 256 + threadIdx.x;
    if (i >= NP * 32) return;
    int row = i >> 5;
    int c4  = i & 31;

    float inv = 1.0f / (g_deg[row] + 1.0f);
    float4 v = ((float4*)out)[i];
    float4 b = ((const float4*)bias)[c4];
    v.x = fmaxf(fmaf(v.x, inv, b.x), 0.f);
    v.y = fmaxf(fmaf(v.y, inv, b.y), 0.f);
    v.z = fmaxf(fmaf(v.z, inv, b.z), 0.f);
    v.w = fmaxf(fmaf(v.w, inv, b.w), 0.f);
    ((float4*)out)[i] = v;
}

// ---------------------------------------------------------------------------
extern "C" void kernel_launch(void* const* d_in, const int* in_sizes, int n_in,
                              void* d_out, int out_size)
{
    const float* x_paper    = (const float*)d_in[0];
    const float* x_author   = (const float*)d_in[1];
    const float* W_cites    = (const float*)d_in[2];
    const float* W_writes   = (const float*)d_in[3];
    const float* W_self     = (const float*)d_in[4];
    const float* bias       = (const float*)d_in[5];
    const int*   cites_src  = (const int*)d_in[6];
    const int*   cites_dst  = (const int*)d_in[7];
    const int*   writes_src = (const int*)d_in[8];
    const int*   writes_dst = (const int*)d_in[9];
    float*       out        = (float*)d_out;

    const int smem_bytes = (DIM * DIM + 64 * DIM) * (int)sizeof(float); // 98304
    cudaFuncSetAttribute(gemm128_kernel,
                         cudaFuncAttributeMaxDynamicSharedMemorySize, smem_bytes);

    void *pHc = nullptr, *pHw = nullptr;
    cudaGetSymbolAddress(&pHc, g_Hc);
    cudaGetSymbolAddress(&pHw, g_Hw);

    // 1. degree accumulator -> 0
    zero_deg_kernel<<<(NP + 255) / 256, 256>>>();

    // 2. GEMMs: self-transform writes d_out directly (accumulator init)
    gemm128_kernel<<<(NP + 63) / 64, 256, smem_bytes>>>(x_paper,  W_self,   out,         NP);
    gemm128_kernel<<<(NP + 63) / 64, 256, smem_bytes>>>(x_paper,  W_cites,  (float*)pHc, NP);
    gemm128_kernel<<<(NA + 63) / 64, 256, smem_bytes>>>(x_author, W_writes, (float*)pHw, NA);

    // 3. edge scatter (vectorized L2 atomics) + fused degree counting
    scatter_kernel<<<EE / 8, 256>>>((const float*)pHc, cites_src,  cites_dst,  out, EE);
    scatter_kernel<<<EE / 8, 256>>>((const float*)pHw, writes_src, writes_dst, out, EE);

    // 4. mean + bias + relu
    finalize_kernel<<<(NP * 32 + 255) / 256, 256>>>(out, bias);
}